// round 3
// baseline (speedup 1.0000x reference)
#include <cuda_runtime.h>
#include <float.h>

#define N_COLS   32000
#define THREADS  512
#define NWARPS   (THREADS / 32)
#define CAND_CAP 6144
#define KREG     32
#define MAX_ROWS 4096

__device__ float g_row_loss[MAX_ROWS];

// Dynamic smem layout: row[N_COLS] | cand[CAND_CAP] | red[64]
#define SMEM_FLOATS (N_COLS + CAND_CAP + 64)

__global__ void __launch_bounds__(THREADS)
entmax15_rows(const float* __restrict__ inp, const int* __restrict__ tgt) {
    extern __shared__ float sm[];
    float* srow  = sm;
    float* scand = sm + N_COLS;
    float* red   = sm + N_COLS + CAND_CAP;
    int*   red_i = reinterpret_cast<int*>(red);

    const int row  = blockIdx.x;
    const int tid  = threadIdx.x;
    const int lane = tid & 31;
    const int w    = tid >> 5;
    const float* rp = inp + (size_t)row * N_COLS;

    // ---- Pass 1: stream row GMEM -> SMEM, track max (input units) ----
    float vmax = -FLT_MAX;
    const float4* g4 = (const float4*)rp;
    float4* s4 = (float4*)srow;
    for (int i = tid; i < N_COLS / 4; i += THREADS) {
        float4 v = g4[i];
        s4[i] = v;
        vmax = fmaxf(fmaxf(vmax, v.x), fmaxf(v.y, fmaxf(v.z, v.w)));
    }
    #pragma unroll
    for (int o = 16; o; o >>= 1) vmax = fmaxf(vmax, __shfl_xor_sync(0xffffffffu, vmax, o));
    if (lane == 0) red[w] = vmax;
    __syncthreads();
    float m = red[0];
    #pragma unroll
    for (int k = 1; k < NWARPS; ++k) m = fmaxf(m, red[k]);
    __syncthreads();  // everyone has m before red[] is reused by the scan

    // ---- Candidate compaction (deterministic, scan-based) ----
    // Support requires X = (v - m)/2 >= -1  <=>  v >= m - 2
    const float thr = m - 2.0f;
    int c = 0;
    for (int i = tid; i < N_COLS; i += THREADS)
        if (srow[i] >= thr) c++;

    // inclusive warp scan of per-thread counts
    int ws = c;
    #pragma unroll
    for (int o = 1; o < 32; o <<= 1) {
        int t = __shfl_up_sync(0xffffffffu, ws, o);
        if (lane >= o) ws += t;
    }
    if (lane == 31) red_i[w] = ws;
    __syncthreads();
    if (w == 0) {
        int t = (lane < NWARPS) ? red_i[lane] : 0;
        #pragma unroll
        for (int o = 1; o < NWARPS; o <<= 1) {
            int u = __shfl_up_sync(0xffffffffu, t, o);
            if (lane >= o) t += u;
        }
        if (lane < NWARPS) red_i[lane] = t;  // inclusive scan of warp totals
    }
    __syncthreads();
    const int base = ((w > 0) ? red_i[w - 1] : 0) + (ws - c);
    const int cnt  = red_i[NWARPS - 1];

    int off = base;
    for (int i = tid; i < N_COLS; i += THREADS) {
        float v = srow[i];
        if (v >= thr) {
            if (off < CAND_CAP) scand[off] = (v - m) * 0.5f;  // X value
            off++;
        }
    }
    __syncthreads();

    // Target logit: clamp index defensively (valid data is always in range,
    // so this never changes a correct result; it converts a bad-dtype bug
    // into a visible rel_err instead of an illegal access).
    int ti = tgt[row];
    ti = (ti < 0) ? 0 : ((ti >= N_COLS) ? N_COLS - 1 : ti);
    const float tg_logit = srow[ti];

    if (cnt <= CAND_CAP) {
        // ---- Warp-0 bisection on register-cached candidates ----
        if (w == 0) {
            float xc[KREG];
            int nm = 0;
            const bool cached = (cnt <= 32 * KREG);
            if (cached)
                for (int i = lane; i < cnt; i += 32) xc[nm++] = scand[i];

            float lo = -1.0f, hi = 0.0f;
            for (int it = 0; it < 30; ++it) {
                float mid = 0.5f * (lo + hi);
                float s = 0.0f;
                if (cached) {
                    #pragma unroll
                    for (int j = 0; j < KREG; ++j)
                        if (j < nm) {
                            float d = xc[j] - mid;
                            if (d > 0.0f) s = fmaf(d, d, s);
                        }
                } else {
                    for (int i = lane; i < cnt; i += 32) {
                        float d = scand[i] - mid;
                        if (d > 0.0f) s = fmaf(d, d, s);
                    }
                }
                #pragma unroll
                for (int o = 16; o; o >>= 1) s += __shfl_xor_sync(0xffffffffu, s, o);
                if (s >= 1.0f) lo = mid; else hi = mid;
            }
            const float tau = 0.5f * (lo + hi);

            float sp = 0.0f, s15 = 0.0f, spx = 0.0f;
            if (cached) {
                #pragma unroll
                for (int j = 0; j < KREG; ++j)
                    if (j < nm) {
                        float x = xc[j], d = x - tau;
                        if (d > 0.0f) { float p = d * d; sp += p; s15 = fmaf(p, d, s15); spx = fmaf(p, x, spx); }
                    }
            } else {
                for (int i = lane; i < cnt; i += 32) {
                    float x = scand[i], d = x - tau;
                    if (d > 0.0f) { float p = d * d; sp += p; s15 = fmaf(p, d, s15); spx = fmaf(p, x, spx); }
                }
            }
            #pragma unroll
            for (int o = 16; o; o >>= 1) {
                sp  += __shfl_xor_sync(0xffffffffu, sp,  o);
                s15 += __shfl_xor_sync(0xffffffffu, s15, o);
                spx += __shfl_xor_sync(0xffffffffu, spx, o);
            }
            if (lane == 0) {
                float omega = (1.0f - s15) * (4.0f / 3.0f);
                g_row_loss[row] = omega + 2.0f * spx + m * sp - tg_logit;
            }
        }
    } else {
        // ---- Fallback (never expected): block-wide bisection over full row ----
        float lo = -1.0f, hi = 0.0f;
        for (int it = 0; it < 30; ++it) {
            float mid = 0.5f * (lo + hi);
            float s = 0.0f;
            for (int i = tid; i < N_COLS; i += THREADS) {
                float d = (srow[i] - m) * 0.5f - mid;
                if (d > 0.0f) s = fmaf(d, d, s);
            }
            #pragma unroll
            for (int o = 16; o; o >>= 1) s += __shfl_xor_sync(0xffffffffu, s, o);
            if (lane == 0) red[w] = s;
            __syncthreads();
            float tot = 0.0f;
            #pragma unroll
            for (int k = 0; k < NWARPS; ++k) tot += red[k];
            __syncthreads();
            if (tot >= 1.0f) lo = mid; else hi = mid;
        }
        const float tau = 0.5f * (lo + hi);
        float sp = 0.0f, s15 = 0.0f, spx = 0.0f;
        for (int i = tid; i < N_COLS; i += THREADS) {
            float x = (srow[i] - m) * 0.5f, d = x - tau;
            if (d > 0.0f) { float p = d * d; sp += p; s15 = fmaf(p, d, s15); spx = fmaf(p, x, spx); }
        }
        #pragma unroll
        for (int o = 16; o; o >>= 1) {
            sp  += __shfl_xor_sync(0xffffffffu, sp,  o);
            s15 += __shfl_xor_sync(0xffffffffu, s15, o);
            spx += __shfl_xor_sync(0xffffffffu, spx, o);
        }
        if (lane == 0) { red[w] = sp; red[16 + w] = s15; red[32 + w] = spx; }
        __syncthreads();
        if (tid == 0) {
            float SP = 0, S15 = 0, SPX = 0;
            #pragma unroll
            for (int k = 0; k < NWARPS; ++k) { SP += red[k]; S15 += red[16 + k]; SPX += red[32 + k]; }
            float omega = (1.0f - S15) * (4.0f / 3.0f);
            g_row_loss[row] = omega + 2.0f * SPX + m * SP - tg_logit;
        }
    }
}

__global__ void reduce_loss(float* __restrict__ out, int n) {
    __shared__ float s[1024];
    float v = 0.0f;
    for (int i = threadIdx.x; i < n; i += 1024) v += g_row_loss[i];
    s[threadIdx.x] = v;
    __syncthreads();
    #pragma unroll
    for (int st = 512; st; st >>= 1) {
        if (threadIdx.x < st) s[threadIdx.x] += s[threadIdx.x + st];
        __syncthreads();
    }
    if (threadIdx.x == 0) out[0] = s[0] / (float)n;
}

extern "C" void kernel_launch(void* const* d_in, const int* in_sizes, int n_in,
                              void* d_out, int out_size) {
    const float* inp = (const float*)d_in[0];
    const int*   tgt = (const int*)d_in[1];
    float*       out = (float*)d_out;
    const int rows = in_sizes[1];  // 4096

    const int smem_bytes = SMEM_FLOATS * (int)sizeof(float);
    cudaFuncSetAttribute(entmax15_rows, cudaFuncAttributeMaxDynamicSharedMemorySize, smem_bytes);

    entmax15_rows<<<rows, THREADS, smem_bytes>>>(inp, tgt);
    reduce_loss<<<1, 1024>>>(out, rows);
}

// round 4
// speedup vs baseline: 3.0248x; 3.0248x over previous
#include <cuda_runtime.h>
#include <float.h>

#define N_COLS   32000
#define NV4      (N_COLS / 4)      // 8000 = 31*256 + 64 (2 full warps on last iter)
#define THREADS  256
#define NWARPS   (THREADS / 32)
#define SEG_CAP  512               // per-warp candidate capacity
#define NR       8                 // per-thread register candidate cache
#define MAX_ROWS 4096
#define BITERS   26

__device__ float g_row_loss[MAX_ROWS];

__global__ void __launch_bounds__(THREADS, 4)
entmax15_rows(const float* __restrict__ inp, const int* __restrict__ tgt) {
    __shared__ float scand[NWARPS * SEG_CAP];   // 16 KB
    __shared__ int   wcnt[NWARPS];
    __shared__ float red[3 * NWARPS];

    const int row  = blockIdx.x;
    const int tid  = threadIdx.x;
    const int lane = tid & 31;
    const int w    = tid >> 5;
    const float* rp = inp + (size_t)row * N_COLS;
    const float4* g4 = (const float4*)rp;

    // ---- Pass 1 (DRAM): row max only. Pure load chain -> high MLP. ----
    float vmax = -FLT_MAX;
    #pragma unroll 4
    for (int i = tid; i < NV4; i += THREADS) {
        float4 v = g4[i];
        vmax = fmaxf(fmaxf(vmax, v.x), fmaxf(v.y, fmaxf(v.z, v.w)));
    }
    #pragma unroll
    for (int o = 16; o; o >>= 1) vmax = fmaxf(vmax, __shfl_xor_sync(0xffffffffu, vmax, o));
    if (lane == 0) red[w] = vmax;
    __syncthreads();
    float m = red[0];
    #pragma unroll
    for (int k = 1; k < NWARPS; ++k) m = fmaxf(m, red[k]);
    __syncthreads();

    // ---- Pass 2 (L2): single-sweep per-warp ordered compaction ----
    // Support requires X = (v-m)/2 >= -1  <=>  v >= m - 2
    const float thr = m - 2.0f;
    int cw = 0;  // this warp's candidate count
    for (int i = tid; i < NV4; i += THREADS) {      // whole warps per iteration
        float4 v = g4[i];
        float xs[4] = {v.x, v.y, v.z, v.w};
        #pragma unroll
        for (int c = 0; c < 4; ++c) {
            bool p = xs[c] >= thr;
            unsigned b = __ballot_sync(0xffffffffu, p);
            if (p) {
                int pos = cw + __popc(b & ((1u << lane) - 1u));
                if (pos < SEG_CAP) scand[w * SEG_CAP + pos] = (xs[c] - m) * 0.5f;
            }
            cw += __popc(b);
        }
    }
    if (lane == 0) wcnt[w] = cw;
    __syncthreads();

    bool ovf = false;
    #pragma unroll
    for (int k = 0; k < NWARPS; ++k) ovf |= (wcnt[k] > SEG_CAP);

    const int ti = tgt[row];
    const float tg_logit = __ldg(rp + ((ti < 0) ? 0 : (ti >= N_COLS ? N_COLS - 1 : ti)));

    if (!ovf) {
        // ---- Block-wide bisection on register-cached candidates ----
        // Each thread caches its warp's segment entries lane, lane+32, ...
        const int mycw = wcnt[w];
        float xc[NR];
        int nm = 0;
        const bool cached = (mycw <= 32 * NR);
        if (cached)
            for (int i = lane; i < mycw; i += 32) xc[nm++] = scand[w * SEG_CAP + i];

        float lo = -1.0f, hi = 0.0f;
        for (int it = 0; it < BITERS; ++it) {
            float mid = 0.5f * (lo + hi);
            float s = 0.0f;
            if (cached) {
                #pragma unroll
                for (int j = 0; j < NR; ++j)
                    if (j < nm) { float d = xc[j] - mid; if (d > 0.0f) s = fmaf(d, d, s); }
            } else {
                for (int i = lane; i < mycw; i += 32) {
                    float d = scand[w * SEG_CAP + i] - mid;
                    if (d > 0.0f) s = fmaf(d, d, s);
                }
            }
            #pragma unroll
            for (int o = 16; o; o >>= 1) s += __shfl_xor_sync(0xffffffffu, s, o);
            if (lane == 0) red[w] = s;
            __syncthreads();
            float tot = 0.0f;
            #pragma unroll
            for (int k = 0; k < NWARPS; ++k) tot += red[k];
            __syncthreads();
            if (tot >= 1.0f) lo = mid; else hi = mid;   // uniform across block
        }
        const float tau = 0.5f * (lo + hi);

        // ---- Final sums (deterministic order) ----
        float sp = 0.0f, s15 = 0.0f, spx = 0.0f;
        if (cached) {
            #pragma unroll
            for (int j = 0; j < NR; ++j)
                if (j < nm) {
                    float x = xc[j], d = x - tau;
                    if (d > 0.0f) { float p = d * d; sp += p; s15 = fmaf(p, d, s15); spx = fmaf(p, x, spx); }
                }
        } else {
            for (int i = lane; i < mycw; i += 32) {
                float x = scand[w * SEG_CAP + i], d = x - tau;
                if (d > 0.0f) { float p = d * d; sp += p; s15 = fmaf(p, d, s15); spx = fmaf(p, x, spx); }
            }
        }
        #pragma unroll
        for (int o = 16; o; o >>= 1) {
            sp  += __shfl_xor_sync(0xffffffffu, sp,  o);
            s15 += __shfl_xor_sync(0xffffffffu, s15, o);
            spx += __shfl_xor_sync(0xffffffffu, spx, o);
        }
        if (lane == 0) { red[w] = sp; red[NWARPS + w] = s15; red[2 * NWARPS + w] = spx; }
        __syncthreads();
        if (tid == 0) {
            float SP = 0, S15 = 0, SPX = 0;
            #pragma unroll
            for (int k = 0; k < NWARPS; ++k) { SP += red[k]; S15 += red[NWARPS + k]; SPX += red[2 * NWARPS + k]; }
            float omega = (1.0f - S15) * (4.0f / 3.0f);
            g_row_loss[row] = omega + 2.0f * SPX + m * SP - tg_logit;
        }
    } else {
        // ---- Fallback (never expected): block-wide bisection over GMEM row (L2) ----
        float lo = -1.0f, hi = 0.0f;
        for (int it = 0; it < BITERS; ++it) {
            float mid = 0.5f * (lo + hi);
            float s = 0.0f;
            for (int i = tid; i < NV4; i += THREADS) {
                float4 v = g4[i];
                float xs[4] = {v.x, v.y, v.z, v.w};
                #pragma unroll
                for (int c = 0; c < 4; ++c) {
                    float d = (xs[c] - m) * 0.5f - mid;
                    if (d > 0.0f) s = fmaf(d, d, s);
                }
            }
            #pragma unroll
            for (int o = 16; o; o >>= 1) s += __shfl_xor_sync(0xffffffffu, s, o);
            if (lane == 0) red[w] = s;
            __syncthreads();
            float tot = 0.0f;
            #pragma unroll
            for (int k = 0; k < NWARPS; ++k) tot += red[k];
            __syncthreads();
            if (tot >= 1.0f) lo = mid; else hi = mid;
        }
        const float tau = 0.5f * (lo + hi);
        float sp = 0.0f, s15 = 0.0f, spx = 0.0f;
        for (int i = tid; i < NV4; i += THREADS) {
            float4 v = g4[i];
            float xs[4] = {v.x, v.y, v.z, v.w};
            #pragma unroll
            for (int c = 0; c < 4; ++c) {
                float x = (xs[c] - m) * 0.5f, d = x - tau;
                if (d > 0.0f) { float p = d * d; sp += p; s15 = fmaf(p, d, s15); spx = fmaf(p, x, spx); }
            }
        }
        #pragma unroll
        for (int o = 16; o; o >>= 1) {
            sp  += __shfl_xor_sync(0xffffffffu, sp,  o);
            s15 += __shfl_xor_sync(0xffffffffu, s15, o);
            spx += __shfl_xor_sync(0xffffffffu, spx, o);
        }
        if (lane == 0) { red[w] = sp; red[NWARPS + w] = s15; red[2 * NWARPS + w] = spx; }
        __syncthreads();
        if (tid == 0) {
            float SP = 0, S15 = 0, SPX = 0;
            #pragma unroll
            for (int k = 0; k < NWARPS; ++k) { SP += red[k]; S15 += red[NWARPS + k]; SPX += red[2 * NWARPS + k]; }
            float omega = (1.0f - S15) * (4.0f / 3.0f);
            g_row_loss[row] = omega + 2.0f * SPX + m * SP - tg_logit;
        }
    }
}

__global__ void reduce_loss(float* __restrict__ out, int n) {
    __shared__ float s[1024];
    float v = 0.0f;
    for (int i = threadIdx.x; i < n; i += 1024) v += g_row_loss[i];
    s[threadIdx.x] = v;
    __syncthreads();
    #pragma unroll
    for (int st = 512; st; st >>= 1) {
        if (threadIdx.x < st) s[threadIdx.x] += s[threadIdx.x + st];
        __syncthreads();
    }
    if (threadIdx.x == 0) out[0] = s[0] / (float)n;
}

extern "C" void kernel_launch(void* const* d_in, const int* in_sizes, int n_in,
                              void* d_out, int out_size) {
    const float* inp = (const float*)d_in[0];
    const int*   tgt = (const int*)d_in[1];
    float*       out = (float*)d_out;
    const int rows = in_sizes[1];  // 4096

    entmax15_rows<<<rows, THREADS>>>(inp, tgt);
    reduce_loss<<<1, 1024>>>(out, rows);
}